// round 2
// baseline (speedup 1.0000x reference)
#include <cuda_runtime.h>

#define HIDDEN 1024
#define HEADS 16
#define HEAD_DIM 64
#define BATCH 4
#define SEQ 2048
#define BSZ (BATCH * SEQ) /* 8192 rows */

// Scratch for projected Q, K, V (32 MB each). __device__ globals: allocation-guard safe.
__device__ float g_q[(size_t)BSZ * HIDDEN];
__device__ float g_k[(size_t)BSZ * HIDDEN];
__device__ float g_v[(size_t)BSZ * HIDDEN];

// ---------------------------------------------------------------------------
// Projection GEMM: C = X @ W + b    X:[8192,1024]  W:[1024,1024]  (row-major)
// 128x128 block tile, BK=8, 256 threads, 8x8 per-thread split microtile.
// blockIdx.z selects which of Q/K/V projection this block computes.
// ---------------------------------------------------------------------------
#define PBM 128
#define PBN 128
#define PBK 8

__global__ __launch_bounds__(256) void proj_kernel(
    const float* __restrict__ xq, const float* __restrict__ xk, const float* __restrict__ xv,
    const float* __restrict__ wq, const float* __restrict__ bq,
    const float* __restrict__ wk, const float* __restrict__ bk,
    const float* __restrict__ wv, const float* __restrict__ bv)
{
    const float* X; const float* W; const float* bias; float* C;
    if (blockIdx.z == 0)      { X = xq; W = wq; bias = bq; C = g_q; }
    else if (blockIdx.z == 1) { X = xk; W = wk; bias = bk; C = g_k; }
    else                      { X = xv; W = wv; bias = bv; C = g_v; }

    __shared__ float As[PBK][PBM];   // transposed A tile: [k][m]
    __shared__ float Bs[PBK][PBN];   // [k][n]

    const int tid = threadIdx.x;
    const int tx = tid & 15;         // 0..15 -> column group
    const int ty = tid >> 4;         // 0..15 -> row group
    const int m0 = blockIdx.y * PBM;
    const int n0 = blockIdx.x * PBN;

    // Load indices: A tile 128x8 -> 256 float4 (each thread 1); B tile 8x128 -> same.
    const int a_row = tid >> 1;          // 0..127
    const int a_seg = (tid & 1) * 4;     // 0 or 4
    const int b_row = tid >> 5;          // 0..7 (warp uniform)
    const int b_col = (tid & 31) * 4;    // 0..124

    float acc[8][8];
    #pragma unroll
    for (int i = 0; i < 8; ++i)
        #pragma unroll
        for (int j = 0; j < 8; ++j) acc[i][j] = 0.0f;

    for (int k0 = 0; k0 < HIDDEN; k0 += PBK) {
        float4 av = *(const float4*)&X[(size_t)(m0 + a_row) * HIDDEN + k0 + a_seg];
        As[a_seg + 0][a_row] = av.x;
        As[a_seg + 1][a_row] = av.y;
        As[a_seg + 2][a_row] = av.z;
        As[a_seg + 3][a_row] = av.w;
        *(float4*)&Bs[b_row][b_col] =
            *(const float4*)&W[(size_t)(k0 + b_row) * HIDDEN + n0 + b_col];
        __syncthreads();

        #pragma unroll
        for (int kk = 0; kk < PBK; ++kk) {
            // Split microtile: rows {ty*4..+3, 64+ty*4..+3}, cols {tx*4..+3, 64+tx*4..+3}
            float4 a0 = *(const float4*)&As[kk][ty * 4];
            float4 a1 = *(const float4*)&As[kk][64 + ty * 4];
            float4 b0 = *(const float4*)&Bs[kk][tx * 4];
            float4 b1 = *(const float4*)&Bs[kk][64 + tx * 4];
            float a[8] = {a0.x, a0.y, a0.z, a0.w, a1.x, a1.y, a1.z, a1.w};
            float b[8] = {b0.x, b0.y, b0.z, b0.w, b1.x, b1.y, b1.z, b1.w};
            #pragma unroll
            for (int i = 0; i < 8; ++i)
                #pragma unroll
                for (int j = 0; j < 8; ++j)
                    acc[i][j] += a[i] * b[j];
        }
        __syncthreads();
    }

    // Epilogue: fused bias, vectorized stores. Row/col split matches microtile.
    #pragma unroll
    for (int ig = 0; ig < 2; ++ig) {
        #pragma unroll
        for (int i = 0; i < 4; ++i) {
            const int m = m0 + ig * 64 + ty * 4 + i;
            #pragma unroll
            for (int jg = 0; jg < 2; ++jg) {
                const int n = n0 + jg * 64 + tx * 4;
                float4 o;
                o.x = acc[ig * 4 + i][jg * 4 + 0] + bias[n + 0];
                o.y = acc[ig * 4 + i][jg * 4 + 1] + bias[n + 1];
                o.z = acc[ig * 4 + i][jg * 4 + 2] + bias[n + 2];
                o.w = acc[ig * 4 + i][jg * 4 + 3] + bias[n + 3];
                *(float4*)&C[(size_t)m * HIDDEN + n] = o;
            }
        }
    }
}

// ---------------------------------------------------------------------------
// Attention (no softmax — faithful to reference bug):
//   O[b,h] = (Q[b,h] @ K[b,h]^T * scale) @ V[b,h]
// Streamed over 64-row K/V blocks. Per block: 64 q-rows of one (b,h).
// Smem: Qt [d][q] (16KB) + KtSt union (Kt [d][kc] -> St [kc][q], 16KB) +
//       Vs [kr][d] (16KB) = 48KB static exactly.
// ---------------------------------------------------------------------------
#define QT 64
#define KT 64

__global__ __launch_bounds__(256) void attn_kernel(float* __restrict__ out)
{
    __shared__ float Qt[64 * 64];    // [d][q]
    __shared__ float KtSt[64 * 64];  // phase A: K^T [d][kc]; phase B: S^T [kc][q]
    __shared__ float Vs[64 * 64];    // [kr][d]

    const int tid = threadIdx.x;
    const int b  = blockIdx.z;
    const int h  = blockIdx.y;
    const int qbase = blockIdx.x * QT;

    const size_t head_off = (size_t)b * SEQ * HIDDEN + (size_t)h * HEAD_DIM;
    const float* Qg = g_q + head_off;
    const float* Kg = g_k + head_off;
    const float* Vg = g_v + head_off;

    const int qi = tid >> 4;      // 0..15
    const int ci = tid & 15;      // 0..15
    const int q0 = qi * 4;
    const int c0 = ci * 4;

    const float scale = 0.125f;   // 1/sqrt(64)

    // Load Q tile transposed: Qt[d][q]
    #pragma unroll
    for (int rep = 0; rep < 4; ++rep) {
        const int idx = tid + rep * 256;       // 0..1023
        const int q  = idx >> 4;               // 0..63
        const int d0 = (idx & 15) * 4;         // 0..60
        float4 v = *(const float4*)&Qg[(size_t)(qbase + q) * HIDDEN + d0];
        Qt[(d0 + 0) * 64 + q] = v.x;
        Qt[(d0 + 1) * 64 + q] = v.y;
        Qt[(d0 + 2) * 64 + q] = v.z;
        Qt[(d0 + 3) * 64 + q] = v.w;
    }

    float o[4][4];
    #pragma unroll
    for (int i = 0; i < 4; ++i)
        #pragma unroll
        for (int j = 0; j < 4; ++j) o[i][j] = 0.0f;

    for (int kb = 0; kb < SEQ / KT; ++kb) {
        const int kbase = kb * KT;

        __syncthreads();  // previous stage2 done reading KtSt/Vs (covers Qt on iter 0)

        // Load K block transposed (Kt[d][kc]) and V block natural (Vs[kr][d])
        #pragma unroll
        for (int rep = 0; rep < 4; ++rep) {
            const int idx = tid + rep * 256;
            const int r  = idx >> 4;
            const int d0 = (idx & 15) * 4;
            float4 kv = *(const float4*)&Kg[(size_t)(kbase + r) * HIDDEN + d0];
            KtSt[(d0 + 0) * 64 + r] = kv.x;
            KtSt[(d0 + 1) * 64 + r] = kv.y;
            KtSt[(d0 + 2) * 64 + r] = kv.z;
            KtSt[(d0 + 3) * 64 + r] = kv.w;
            *(float4*)&Vs[r * 64 + d0] =
                *(const float4*)&Vg[(size_t)(kbase + r) * HIDDEN + d0];
        }
        __syncthreads();

        // Stage 1: s[q][c] = sum_d Qt[d][q] * Kt[d][c]   (row-broadcast loads)
        float s[4][4];
        #pragma unroll
        for (int i = 0; i < 4; ++i)
            #pragma unroll
            for (int j = 0; j < 4; ++j) s[i][j] = 0.0f;

        #pragma unroll 8
        for (int kk = 0; kk < 64; ++kk) {
            float4 a4 = *(const float4*)&Qt[kk * 64 + q0];
            float4 b4 = *(const float4*)&KtSt[kk * 64 + c0];
            float a[4] = {a4.x, a4.y, a4.z, a4.w};
            float bb[4] = {b4.x, b4.y, b4.z, b4.w};
            #pragma unroll
            for (int i = 0; i < 4; ++i)
                #pragma unroll
                for (int j = 0; j < 4; ++j)
                    s[i][j] += a[i] * bb[j];
        }
        __syncthreads();  // all Kt reads complete -> safe to overwrite with S^T

        // Write S^T[kc][q] (scaled)
        #pragma unroll
        for (int j = 0; j < 4; ++j) {
            float4 w4 = make_float4(s[0][j] * scale, s[1][j] * scale,
                                    s[2][j] * scale, s[3][j] * scale);
            *(float4*)&KtSt[(c0 + j) * 64 + q0] = w4;
        }
        __syncthreads();

        // Stage 2: o[q][d] += sum_kr S^T[kr][q] * Vs[kr][d]
        #pragma unroll 8
        for (int j = 0; j < 64; ++j) {
            float4 a4 = *(const float4*)&KtSt[j * 64 + q0];
            float4 b4 = *(const float4*)&Vs[j * 64 + c0];
            float a[4] = {a4.x, a4.y, a4.z, a4.w};
            float bb[4] = {b4.x, b4.y, b4.z, b4.w};
            #pragma unroll
            for (int i = 0; i < 4; ++i)
                #pragma unroll
                for (int jj = 0; jj < 4; ++jj)
                    o[i][jj] += a[i] * bb[jj];
        }
    }

    // Epilogue: out[b, qbase+q0+i, h*64 + c0 .. +3]
    float* Og = out + head_off;
    #pragma unroll
    for (int i = 0; i < 4; ++i) {
        *(float4*)&Og[(size_t)(qbase + q0 + i) * HIDDEN + c0] =
            make_float4(o[i][0], o[i][1], o[i][2], o[i][3]);
    }
}

// ---------------------------------------------------------------------------
extern "C" void kernel_launch(void* const* d_in, const int* in_sizes, int n_in,
                              void* d_out, int out_size)
{
    const float* query = (const float*)d_in[0];
    const float* key   = (const float*)d_in[1];
    const float* value = (const float*)d_in[2];
    const float* q_w   = (const float*)d_in[3];
    const float* q_b   = (const float*)d_in[4];
    const float* k_w   = (const float*)d_in[5];
    const float* k_b   = (const float*)d_in[6];
    const float* v_w   = (const float*)d_in[7];
    const float* v_b   = (const float*)d_in[8];

    dim3 gp(HIDDEN / PBN, BSZ / PBM, 3);   // (8, 64, 3)
    proj_kernel<<<gp, 256>>>(query, key, value, q_w, q_b, k_w, k_b, v_w, v_b);

    dim3 ga(SEQ / QT, HEADS, BATCH);       // (32, 16, 4)
    attn_kernel<<<ga, 256>>>((float*)d_out);
}

// round 3
// speedup vs baseline: 2.9085x; 2.9085x over previous
#include <cuda_runtime.h>

#define HIDDEN 1024
#define HEADS 16
#define HEAD_DIM 64
#define BATCH 4
#define SEQ 2048
#define BSZ (BATCH * SEQ) /* 8192 rows */
#define NSLICE 8          /* split-K slices for K^T V */

// Scratch (__device__ globals: allocation-guard safe)
__device__ float g_k[(size_t)BSZ * HIDDEN];                       // 32 MB K projection
__device__ float g_v[(size_t)BSZ * HIDDEN];                       // 32 MB V projection
__device__ float g_mp[(size_t)NSLICE * 64 * 64 * 64];             //  8 MB partial K^T V
__device__ float g_m[(size_t)64 * 64 * 64];                       //  1 MB M[bh][k][d]
__device__ float g_w2[(size_t)BATCH * HIDDEN * HIDDEN];           // 16 MB folded weights
__device__ float g_b2[(size_t)BATCH * HIDDEN];                    // folded bias

// ---------------------------------------------------------------------------
// Packed fp32x2 FMA helpers (sm_103a FFMA2 path — only reachable via PTX)
// ---------------------------------------------------------------------------
__device__ __forceinline__ unsigned long long pk(float lo, float hi) {
    unsigned long long r;
    asm("mov.b64 %0, {%1, %2};" : "=l"(r) : "f"(lo), "f"(hi));
    return r;
}
__device__ __forceinline__ void upk(unsigned long long v, float& lo, float& hi) {
    asm("mov.b64 {%0, %1}, %2;" : "=f"(lo), "=f"(hi) : "l"(v));
}
__device__ __forceinline__ void ffma2(unsigned long long& d,
                                      unsigned long long a, unsigned long long b) {
    asm("fma.rn.f32x2 %0, %1, %2, %3;" : "=l"(d) : "l"(a), "l"(b), "l"(d));
}

// ---------------------------------------------------------------------------
// GEMM: C = X @ W + bias    X:[8192,1024]  W:[1024,1024]  row-major
// 128x128 tile, BK=8, 256 threads, 8x8 microtile packed into 8x4 f32x2 accs.
// mode 0: blockIdx.z 0 -> key proj (g_k), 1 -> value proj (g_v)
// mode 2: output GEMM  X=query, W=g_w2 (per-batch), bias=g_b2 -> d_out
// ---------------------------------------------------------------------------
#define PBM 128
#define PBN 128
#define PBK 8

__global__ __launch_bounds__(256) void gemm_kernel(
    const float* __restrict__ xk, const float* __restrict__ xv,
    const float* __restrict__ xq,
    const float* __restrict__ kw, const float* __restrict__ kb,
    const float* __restrict__ vw, const float* __restrict__ vb,
    float* __restrict__ out, int mode)
{
    const float* X; const float* W; const float* bias; float* C;
    if (mode == 0) {
        if (blockIdx.z == 0) { X = xk; W = kw; bias = kb; C = g_k; }
        else                 { X = xv; W = vw; bias = vb; C = g_v; }
    } else {
        const int bb = blockIdx.y >> 4;  // 16 row-tiles of 128 per batch
        X = xq;
        W = g_w2 + (size_t)bb * HIDDEN * HIDDEN;
        bias = g_b2 + (size_t)bb * HIDDEN;
        C = out;
    }

    __shared__ float As[PBK][PBM];   // transposed A tile [k][m]
    __shared__ float Bs[PBK][PBN];   // [k][n]

    const int tid = threadIdx.x;
    const int tx = tid & 15;
    const int ty = tid >> 4;
    const int m0 = blockIdx.y * PBM;
    const int n0 = blockIdx.x * PBN;

    const int a_row = tid >> 1;
    const int a_seg = (tid & 1) * 4;
    const int b_row = tid >> 5;
    const int b_col = (tid & 31) * 4;

    unsigned long long acc2[8][4];
    #pragma unroll
    for (int i = 0; i < 8; ++i)
        #pragma unroll
        for (int j = 0; j < 4; ++j) acc2[i][j] = 0ULL;

    for (int k0 = 0; k0 < HIDDEN; k0 += PBK) {
        float4 av = *(const float4*)&X[(size_t)(m0 + a_row) * HIDDEN + k0 + a_seg];
        As[a_seg + 0][a_row] = av.x;
        As[a_seg + 1][a_row] = av.y;
        As[a_seg + 2][a_row] = av.z;
        As[a_seg + 3][a_row] = av.w;
        *(float4*)&Bs[b_row][b_col] =
            *(const float4*)&W[(size_t)(k0 + b_row) * HIDDEN + n0 + b_col];
        __syncthreads();

        #pragma unroll
        for (int kk = 0; kk < PBK; ++kk) {
            float4 a0 = *(const float4*)&As[kk][ty * 4];
            float4 a1 = *(const float4*)&As[kk][64 + ty * 4];
            float4 b0 = *(const float4*)&Bs[kk][tx * 4];
            float4 b1 = *(const float4*)&Bs[kk][64 + tx * 4];
            unsigned long long bp[4] = { pk(b0.x, b0.y), pk(b0.z, b0.w),
                                         pk(b1.x, b1.y), pk(b1.z, b1.w) };
            float a[8] = {a0.x, a0.y, a0.z, a0.w, a1.x, a1.y, a1.z, a1.w};
            #pragma unroll
            for (int i = 0; i < 8; ++i) {
                unsigned long long ap = pk(a[i], a[i]);
                #pragma unroll
                for (int j = 0; j < 4; ++j) ffma2(acc2[i][j], ap, bp[j]);
            }
        }
        __syncthreads();
    }

    // Epilogue: unpack, fused bias, float4 stores
    #pragma unroll
    for (int ig = 0; ig < 2; ++ig) {
        #pragma unroll
        for (int i = 0; i < 4; ++i) {
            const int m = m0 + ig * 64 + ty * 4 + i;
            #pragma unroll
            for (int jg = 0; jg < 2; ++jg) {
                const int n = n0 + jg * 64 + tx * 4;
                float c0, c1, c2, c3;
                upk(acc2[ig * 4 + i][jg * 2 + 0], c0, c1);
                upk(acc2[ig * 4 + i][jg * 2 + 1], c2, c3);
                float4 o;
                o.x = c0 + bias[n + 0];
                o.y = c1 + bias[n + 1];
                o.z = c2 + bias[n + 2];
                o.w = c3 + bias[n + 3];
                *(float4*)&C[(size_t)m * HIDDEN + n] = o;
            }
        }
    }
}

// ---------------------------------------------------------------------------
// m_partial: P[s][bh][k][d] = sum_{r in 256-row slice s} K[r,k] * V[r,d]
// grid (NSLICE, 64), 256 threads; 4x4 microtile of the 64x64 output.
// ---------------------------------------------------------------------------
__global__ __launch_bounds__(256) void m_partial_kernel()
{
    const int s  = blockIdx.x;
    const int bh = blockIdx.y;
    const int b = bh >> 4, h = bh & 15;
    const size_t head_off = (size_t)b * SEQ * HIDDEN + (size_t)h * HEAD_DIM;
    const float* Kg = g_k + head_off;
    const float* Vg = g_v + head_off;

    __shared__ float Ks[16][64];
    __shared__ float Vs[16][64];

    const int tid = threadIdx.x;
    const int k0 = (tid >> 4) * 4;
    const int d0 = (tid & 15) * 4;
    const int lr = tid >> 4;          // load row 0..15
    const int ld = (tid & 15) * 4;    // load col group

    float acc[4][4];
    #pragma unroll
    for (int i = 0; i < 4; ++i)
        #pragma unroll
        for (int j = 0; j < 4; ++j) acc[i][j] = 0.0f;

    const int rbeg = s * (SEQ / NSLICE);
    for (int r0 = rbeg; r0 < rbeg + SEQ / NSLICE; r0 += 16) {
        __syncthreads();
        *(float4*)&Ks[lr][ld] = *(const float4*)&Kg[(size_t)(r0 + lr) * HIDDEN + ld];
        *(float4*)&Vs[lr][ld] = *(const float4*)&Vg[(size_t)(r0 + lr) * HIDDEN + ld];
        __syncthreads();

        #pragma unroll
        for (int rr = 0; rr < 16; ++rr) {
            float4 a4 = *(const float4*)&Ks[rr][k0];
            float4 b4 = *(const float4*)&Vs[rr][d0];
            float a[4] = {a4.x, a4.y, a4.z, a4.w};
            float bb[4] = {b4.x, b4.y, b4.z, b4.w};
            #pragma unroll
            for (int i = 0; i < 4; ++i)
                #pragma unroll
                for (int j = 0; j < 4; ++j)
                    acc[i][j] += a[i] * bb[j];
        }
    }

    float* P = g_mp + ((size_t)s * 64 + bh) * 4096;
    #pragma unroll
    for (int i = 0; i < 4; ++i)
        *(float4*)&P[(k0 + i) * 64 + d0] =
            make_float4(acc[i][0], acc[i][1], acc[i][2], acc[i][3]);
}

// ---------------------------------------------------------------------------
// m_reduce: M[bh][k][d] = sum_s P[s][bh][k][d]    (64*4096 outputs)
// ---------------------------------------------------------------------------
__global__ __launch_bounds__(256) void m_reduce_kernel()
{
    const int idx = blockIdx.x * 256 + threadIdx.x;  // 0 .. 64*4096-1
    float sum = 0.0f;
    #pragma unroll
    for (int s = 0; s < NSLICE; ++s)
        sum += g_mp[(size_t)s * 64 * 4096 + idx];
    g_m[idx] = sum;
}

// ---------------------------------------------------------------------------
// fold_w: W2[b][i][h*64+d] = scale * sum_k Wq[i][h*64+k] * M[b*16+h][k][d]
// grid (8 row-tiles, 16 heads, 4 batches), 256 threads, 8x4 microtile.
// ---------------------------------------------------------------------------
__global__ __launch_bounds__(256) void fold_w_kernel(const float* __restrict__ qw)
{
    const int it = blockIdx.x;   // 128-row tile of W
    const int h  = blockIdx.y;
    const int b  = blockIdx.z;
    const float scale = 0.125f;  // 1/sqrt(64)

    __shared__ float Wt[64][128];  // transposed Wq tile [k][i]
    __shared__ float Ms[64][64];   // scaled M

    const int tid = threadIdx.x;
    const float* Mg = g_m + ((size_t)(b * 16 + h)) * 4096;

    // Load Ms (scaled): 4096 floats = 1024 float4, 4 per thread
    #pragma unroll
    for (int rep = 0; rep < 4; ++rep) {
        const int idx = tid + rep * 256;
        const int r = idx >> 4, c = (idx & 15) * 4;
        float4 v = *(const float4*)&Mg[r * 64 + c];
        Ms[r][c + 0] = v.x * scale;
        Ms[r][c + 1] = v.y * scale;
        Ms[r][c + 2] = v.z * scale;
        Ms[r][c + 3] = v.w * scale;
    }
    // Load Wq tile transposed: 128x64 floats = 2048 float4, 8 per thread
    #pragma unroll
    for (int rep = 0; rep < 8; ++rep) {
        const int idx = tid + rep * 256;
        const int i = idx >> 4, kk0 = (idx & 15) * 4;
        float4 w = *(const float4*)&qw[(size_t)(it * 128 + i) * HIDDEN + h * 64 + kk0];
        Wt[kk0 + 0][i] = w.x;
        Wt[kk0 + 1][i] = w.y;
        Wt[kk0 + 2][i] = w.z;
        Wt[kk0 + 3][i] = w.w;
    }
    __syncthreads();

    const int i0 = (tid >> 4) * 8;
    const int d0 = (tid & 15) * 4;

    float acc[8][4];
    #pragma unroll
    for (int i = 0; i < 8; ++i)
        #pragma unroll
        for (int j = 0; j < 4; ++j) acc[i][j] = 0.0f;

    #pragma unroll 8
    for (int kk = 0; kk < 64; ++kk) {
        float4 a0 = *(const float4*)&Wt[kk][i0];
        float4 a1 = *(const float4*)&Wt[kk][i0 + 4];
        float4 b4 = *(const float4*)&Ms[kk][d0];
        float a[8] = {a0.x, a0.y, a0.z, a0.w, a1.x, a1.y, a1.z, a1.w};
        float bb[4] = {b4.x, b4.y, b4.z, b4.w};
        #pragma unroll
        for (int i = 0; i < 8; ++i)
            #pragma unroll
            for (int j = 0; j < 4; ++j)
                acc[i][j] += a[i] * bb[j];
    }

    float* W2 = g_w2 + (size_t)b * HIDDEN * HIDDEN;
    #pragma unroll
    for (int i = 0; i < 8; ++i)
        *(float4*)&W2[(size_t)(it * 128 + i0 + i) * HIDDEN + h * 64 + d0] =
            make_float4(acc[i][0], acc[i][1], acc[i][2], acc[i][3]);
}

// ---------------------------------------------------------------------------
// fold_b: b2[b][h*64+d] = scale * sum_k qb[h*64+k] * M[b*16+h][k][d]
// ---------------------------------------------------------------------------
__global__ __launch_bounds__(256) void fold_b_kernel(const float* __restrict__ qb)
{
    const int idx = blockIdx.x * 256 + threadIdx.x;  // 0..4095
    const int b = idx >> 10;
    const int hd = idx & 1023;
    const int h = hd >> 6, d = hd & 63;
    const float scale = 0.125f;
    const float* M = g_m + ((size_t)(b * 16 + h)) * 4096;
    float sum = 0.0f;
    #pragma unroll
    for (int k = 0; k < 64; ++k)
        sum += qb[h * 64 + k] * M[k * 64 + d];
    g_b2[idx] = sum * scale;
}

// ---------------------------------------------------------------------------
extern "C" void kernel_launch(void* const* d_in, const int* in_sizes, int n_in,
                              void* d_out, int out_size)
{
    const float* query = (const float*)d_in[0];
    const float* key   = (const float*)d_in[1];
    const float* value = (const float*)d_in[2];
    const float* q_w   = (const float*)d_in[3];
    const float* q_b   = (const float*)d_in[4];
    const float* k_w   = (const float*)d_in[5];
    const float* k_b   = (const float*)d_in[6];
    const float* v_w   = (const float*)d_in[7];
    const float* v_b   = (const float*)d_in[8];
    float* out = (float*)d_out;

    // 1) K and V projections
    dim3 gp(HIDDEN / PBN, BSZ / PBM, 2);   // (8, 64, 2)
    gemm_kernel<<<gp, 256>>>(key, value, query, k_w, k_b, v_w, v_b, out, 0);

    // 2) M = K^T V per (b,h), split-K partials + reduce
    m_partial_kernel<<<dim3(NSLICE, 64), 256>>>();
    m_reduce_kernel<<<(64 * 4096) / 256, 256>>>();

    // 3) Fold M into the Q projection: W2 = scale * Wq * blockdiag(M), b2 likewise
    fold_w_kernel<<<dim3(8, HEADS, BATCH), 256>>>(q_w);
    fold_b_kernel<<<16, 256>>>(q_b);

    // 4) Output GEMM: out = query @ W2 + b2   (directly into d_out)
    dim3 go(HIDDEN / PBN, BSZ / PBM, 1);
    gemm_kernel<<<go, 256>>>(key, value, query, k_w, k_b, v_w, v_b, out, 2);
}

// round 8
// speedup vs baseline: 4.2683x; 1.4675x over previous
#include <cuda_runtime.h>
#include <cuda_fp16.h>
#include <cstdint>

#define HIDDEN 1024
#define HEADS 16
#define HEAD_DIM 64
#define BATCH 4
#define SEQ 2048
#define BSZ (BATCH * SEQ) /* 8192 */
#define NSLICE 8

// ---------------- scratch (__device__ globals: allocation-guard safe) ------
// NOTE: these symbols are ONLY referenced from device code (never passed as
// kernel arguments from host — host-side symbol addresses are host shadows
// and GB300's ATS silently reads host BSS zeros; that was the R5-R7 bug).
__device__ __align__(16) __half g_qh[(size_t)BSZ * HIDDEN], g_ql[(size_t)BSZ * HIDDEN];
__device__ __align__(16) __half g_kxh[(size_t)BSZ * HIDDEN], g_kxl[(size_t)BSZ * HIDDEN];
__device__ __align__(16) __half g_vxh[(size_t)BSZ * HIDDEN], g_vxl[(size_t)BSZ * HIDDEN];
__device__ __align__(16) __half g_wkh[(size_t)HIDDEN * HIDDEN], g_wkl[(size_t)HIDDEN * HIDDEN];
__device__ __align__(16) __half g_wvh[(size_t)HIDDEN * HIDDEN], g_wvl[(size_t)HIDDEN * HIDDEN];
__device__ __align__(16) __half g_w2h[(size_t)BATCH * HIDDEN * HIDDEN];
__device__ __align__(16) __half g_w2l[(size_t)BATCH * HIDDEN * HIDDEN];
__device__ float g_k[(size_t)BSZ * HIDDEN];   // K projection (fp32)
__device__ float g_v[(size_t)BSZ * HIDDEN];   // V projection (fp32)
__device__ float g_mp[(size_t)NSLICE * 64 * 64 * 64];
__device__ float g_m[(size_t)64 * 64 * 64];
__device__ float g_b2[(size_t)BATCH * HIDDEN];

// ---------------- PTX helpers (compute_103 base-target safe) ---------------
__device__ __forceinline__ uint32_t smem_u32(const void* p) {
    uint32_t a;
    asm("{ .reg .u64 t; cvta.to.shared.u64 t, %1; cvt.u32.u64 %0, t; }" : "=r"(a) : "l"(p));
    return a;
}
__device__ __forceinline__ uint32_t lds32(uint32_t a) {
    uint32_t v;
    asm volatile("ld.shared.b32 %0, [%1];" : "=r"(v) : "r"(a));
    return v;
}
#define MMA16816(d, a, b) \
    asm volatile("mma.sync.aligned.m16n8k16.row.col.f32.f16.f16.f32 " \
        "{%0,%1,%2,%3}, {%4,%5,%6,%7}, {%8,%9}, {%0,%1,%2,%3};" \
        : "+f"((d)[0]), "+f"((d)[1]), "+f"((d)[2]), "+f"((d)[3]) \
        : "r"((a)[0]), "r"((a)[1]), "r"((a)[2]), "r"((a)[3]), \
          "r"((b)[0]), "r"((b)[1]))

// f16 hi/lo split: x = h + l, combined ~22-bit mantissa
struct HF2 { __half h, l; };
__device__ __forceinline__ HF2 hsplit(float x) {
    HF2 r;
    r.h = __float2half_rn(x);
    r.l = __float2half_rn(x - __half2float(r.h));
    return r;
}

// ---------------------------------------------------------------------------
// convert_x: fp32 [8192x1024] -> f16 hi/lo. z: 0=query 1=key 2=value
// ---------------------------------------------------------------------------
__global__ __launch_bounds__(256) void convert_x(
    const float* __restrict__ q, const float* __restrict__ k, const float* __restrict__ v)
{
    const float* x; __half *oh, *ol;
    if (blockIdx.z == 0)      { x = q; oh = g_qh;  ol = g_ql;  }
    else if (blockIdx.z == 1) { x = k; oh = g_kxh; ol = g_kxl; }
    else                      { x = v; oh = g_vxh; ol = g_vxl; }

    const size_t i8 = ((size_t)blockIdx.x * 256 + threadIdx.x) * 8;
    float4 a = *(const float4*)&x[i8];
    float4 b = *(const float4*)&x[i8 + 4];
    float f[8] = {a.x, a.y, a.z, a.w, b.x, b.y, b.z, b.w};
    union U8 { __half v[8]; uint4 u; } uh, ul;
    #pragma unroll
    for (int i = 0; i < 8; ++i) { HF2 s = hsplit(f[i]); uh.v[i] = s.h; ul.v[i] = s.l; }
    *(uint4*)&oh[i8] = uh.u;
    *(uint4*)&ol[i8] = ul.u;
}

// ---------------------------------------------------------------------------
// transpose_w: W[k][n] fp32 -> Wt hi/lo [n][k] f16. z: 0=k_w 1=v_w
// ---------------------------------------------------------------------------
__global__ void transpose_w(const float* __restrict__ kw, const float* __restrict__ vw)
{
    const float* W; __half *oh, *ol;
    if (blockIdx.z == 0) { W = kw; oh = g_wkh; ol = g_wkl; }
    else                 { W = vw; oh = g_wvh; ol = g_wvl; }

    __shared__ float t[32][33];
    const int tx = threadIdx.x, ty = threadIdx.y;
    const int kt = blockIdx.x * 32, nt = blockIdx.y * 32;

    #pragma unroll
    for (int r = 0; r < 4; ++r)
        t[ty + r * 8][tx] = W[(size_t)(kt + ty + r * 8) * HIDDEN + nt + tx];
    __syncthreads();
    #pragma unroll
    for (int r = 0; r < 4; ++r) {
        HF2 s = hsplit(t[tx][ty + r * 8]);
        const size_t o = (size_t)(nt + ty + r * 8) * HIDDEN + kt + tx;
        oh[o] = s.h;
        ol[o] = s.l;
    }
}

// ---------------------------------------------------------------------------
// HMMA GEMM (m16n8k16 f16, fp32 acc, 3-term hi/lo split):
//   C[m][n] = sum_k A[m][k]*B[n][k] + bias[n]
// mode 0: blockIdx.z 0 -> K proj (g_kx* x g_wk* + kb -> g_k)
//                     1 -> V proj (g_vx* x g_wv* + vb -> g_v)
// mode 1: out GEMM (g_q* x g_w2*[batch] + g_b2[batch] -> out)
// All scratch pointers resolved IN DEVICE CODE from global symbols.
// CTA 128x128, 8 warps (2x4), warp tile 64x32, BK=16.
// Register-double-buffered: LDG chunk c+1 while HMMA on chunk c from smem.
// Static smem 48KB. Fragments via plain ld.shared.b32; 48B row stride ->
// banks (12g+t) mod 32 all distinct -> conflict-free.
// ---------------------------------------------------------------------------
#define BK 16
#define RSTR 48                  /* bytes per smem row: 16 f16 + 8 pad */
#define MTILE (128 * RSTR)       /* 6144 B per matrix tile */
#define STAGEB (4 * MTILE)       /* 24576 B: Ah, Al, Bh, Bl */
#define NCH (HIDDEN / BK)        /* 64 chunks */

__global__ __launch_bounds__(256) void gemm3(
    const float* __restrict__ kb, const float* __restrict__ vb,
    float* __restrict__ out, int mode)
{
    __shared__ __align__(16) char sm[2 * STAGEB];   // 49152 B static
    const uint32_t sb = smem_u32(sm);

    const int tid = threadIdx.x;
    const int lane = tid & 31;
    const int g = lane >> 2;         // 0..7
    const int t = lane & 3;          // 0..3
    const int wid = tid >> 5;
    const int warp_m = wid >> 2;     // 0..1
    const int warp_n = wid & 3;      // 0..3
    const int m0 = blockIdx.y * 128;
    const int n0 = blockIdx.x * 128;

    const __half *Ah, *Al, *Bh, *Bl; const float* bias; float* C;
    if (mode == 0) {
        if (blockIdx.z == 0) {
            Ah = g_kxh; Al = g_kxl; Bh = g_wkh; Bl = g_wkl; bias = kb; C = g_k;
        } else {
            Ah = g_vxh; Al = g_vxl; Bh = g_wvh; Bl = g_wvl; bias = vb; C = g_v;
        }
    } else {
        const int bb = m0 >> 11;     // 2048 rows per batch
        Ah = g_qh; Al = g_ql;
        Bh = g_w2h + (size_t)bb * HIDDEN * HIDDEN;
        Bl = g_w2l + (size_t)bb * HIDDEN * HIDDEN;
        bias = g_b2 + (size_t)bb * HIDDEN;
        C = out;
    }

    // Per-thread load slots: idx = tid + it*256 in 0..1023
    //   mat = idx>>8 (0:Ah 1:Al 2:Bh 3:Bl), r = (idx&255)>>1, seg = idx&1
    const int slot_r = (tid & 255) >> 1;   // row 0..127 (same for all it)
    const int slot_s = tid & 1;            // 16B segment

    auto gload = [&](int chunk, uint4* rg) {
        const int k0 = chunk * BK;
        #pragma unroll
        for (int it = 0; it < 4; ++it) {
            const int mat = (tid + it * 256) >> 8;
            const __half* src;
            if (mat == 0)      src = Ah + (size_t)(m0 + slot_r) * HIDDEN;
            else if (mat == 1) src = Al + (size_t)(m0 + slot_r) * HIDDEN;
            else if (mat == 2) src = Bh + (size_t)(n0 + slot_r) * HIDDEN;
            else               src = Bl + (size_t)(n0 + slot_r) * HIDDEN;
            rg[it] = *(const uint4*)(src + k0 + slot_s * 8);
        }
    };
    auto sstore = [&](int stage, const uint4* rg) {
        #pragma unroll
        for (int it = 0; it < 4; ++it) {
            const int mat = (tid + it * 256) >> 8;
            *(uint4*)(sm + stage * STAGEB + mat * MTILE + slot_r * RSTR + slot_s * 16)
                = rg[it];
        }
    };

    float acc[4][4][4];
    #pragma unroll
    for (int i = 0; i < 4; ++i)
        #pragma unroll
        for (int j = 0; j < 4; ++j)
            #pragma unroll
            for (int e = 0; e < 4; ++e) acc[i][j][e] = 0.0f;

    {
        uint4 rg[4];
        gload(0, rg);
        sstore(0, rg);
    }
    __syncthreads();

    for (int c = 0; c < NCH; ++c) {
        uint4 rn[4];
        if (c + 1 < NCH) gload(c + 1, rn);   // LDG in flight over compute

        const uint32_t stg = sb + (c & 1) * STAGEB;

        uint32_t ah[4][4], al[4][4], bh[4][2], bl[4][2];
        #pragma unroll
        for (int i = 0; i < 4; ++i) {
            const uint32_t ra = stg + (warp_m * 64 + i * 16 + g) * RSTR + t * 4;
            ah[i][0] = lds32(ra);
            ah[i][1] = lds32(ra + 8 * RSTR);
            ah[i][2] = lds32(ra + 16);
            ah[i][3] = lds32(ra + 8 * RSTR + 16);
            al[i][0] = lds32(ra + MTILE);
            al[i][1] = lds32(ra + MTILE + 8 * RSTR);
            al[i][2] = lds32(ra + MTILE + 16);
            al[i][3] = lds32(ra + MTILE + 8 * RSTR + 16);
        }
        #pragma unroll
        for (int j = 0; j < 4; ++j) {
            const uint32_t rb = stg + 2 * MTILE + (warp_n * 32 + j * 8 + g) * RSTR + t * 4;
            bh[j][0] = lds32(rb);
            bh[j][1] = lds32(rb + 16);
            bl[j][0] = lds32(rb + MTILE);
            bl[j][1] = lds32(rb + MTILE + 16);
        }
        #pragma unroll
        for (int i = 0; i < 4; ++i)
            #pragma unroll
            for (int j = 0; j < 4; ++j) {
                MMA16816(acc[i][j], ah[i], bh[j]);
                MMA16816(acc[i][j], ah[i], bl[j]);
                MMA16816(acc[i][j], al[i], bh[j]);
            }

        if (c + 1 < NCH) sstore((c + 1) & 1, rn);  // idle stage; disjoint from reads
        __syncthreads();
    }

    // -------- epilogue: bias + fp32 stores --------
    // c0,c1 -> row g, cols 2t,2t+1 ; c2,c3 -> row g+8
    #pragma unroll
    for (int j = 0; j < 4; ++j) {
        const int col = n0 + warp_n * 32 + j * 8 + t * 2;
        const float2 bv = *(const float2*)&bias[col];
        #pragma unroll
        for (int i = 0; i < 4; ++i) {
            const int row = m0 + warp_m * 64 + i * 16 + g;
            float2 v0 = make_float2(acc[i][j][0] + bv.x, acc[i][j][1] + bv.y);
            float2 v1 = make_float2(acc[i][j][2] + bv.x, acc[i][j][3] + bv.y);
            *(float2*)&C[(size_t)row * HIDDEN + col] = v0;
            *(float2*)&C[(size_t)(row + 8) * HIDDEN + col] = v1;
        }
    }
}

// ---------------------------------------------------------------------------
// m_partial / m_reduce: M[bh] = K^T V  (fp32, proven in round 3)
// ---------------------------------------------------------------------------
__global__ __launch_bounds__(256) void m_partial_kernel()
{
    const int s = blockIdx.x, bh = blockIdx.y;
    const int b = bh >> 4, h = bh & 15;
    const size_t off = (size_t)b * SEQ * HIDDEN + (size_t)h * HEAD_DIM;
    const float* Kg = g_k + off;
    const float* Vg = g_v + off;

    __shared__ float Ks[16][64], Vs[16][64];
    const int tid = threadIdx.x;
    const int k0 = (tid >> 4) * 4, d0 = (tid & 15) * 4;
    const int lr = tid >> 4, ld = (tid & 15) * 4;

    float acc[4][4] = {};
    const int rbeg = s * (SEQ / NSLICE);
    for (int r0 = rbeg; r0 < rbeg + SEQ / NSLICE; r0 += 16) {
        __syncthreads();
        *(float4*)&Ks[lr][ld] = *(const float4*)&Kg[(size_t)(r0 + lr) * HIDDEN + ld];
        *(float4*)&Vs[lr][ld] = *(const float4*)&Vg[(size_t)(r0 + lr) * HIDDEN + ld];
        __syncthreads();
        #pragma unroll
        for (int rr = 0; rr < 16; ++rr) {
            float4 a4 = *(const float4*)&Ks[rr][k0];
            float4 b4 = *(const float4*)&Vs[rr][d0];
            float a[4] = {a4.x, a4.y, a4.z, a4.w};
            float bb[4] = {b4.x, b4.y, b4.z, b4.w};
            #pragma unroll
            for (int i = 0; i < 4; ++i)
                #pragma unroll
                for (int j = 0; j < 4; ++j) acc[i][j] += a[i] * bb[j];
        }
    }
    float* P = g_mp + ((size_t)s * 64 + bh) * 4096;
    #pragma unroll
    for (int i = 0; i < 4; ++i)
        *(float4*)&P[(k0 + i) * 64 + d0] =
            make_float4(acc[i][0], acc[i][1], acc[i][2], acc[i][3]);
}

__global__ __launch_bounds__(256) void m_reduce_kernel()
{
    const int idx = blockIdx.x * 256 + threadIdx.x;
    float s = 0.0f;
    #pragma unroll
    for (int i = 0; i < NSLICE; ++i) s += g_mp[(size_t)i * 64 * 4096 + idx];
    g_m[idx] = s;
}

// ---------------------------------------------------------------------------
// fold_w: W2t[b][n][k] (f16 hi/lo) = (scale * Wq * blockdiag(M))^T
// ---------------------------------------------------------------------------
__global__ __launch_bounds__(256) void fold_w_kernel(const float* __restrict__ qw)
{
    const int it = blockIdx.x, h = blockIdx.y, b = blockIdx.z;
    const float scale = 0.125f;

    __shared__ float Wt[64][128];
    __shared__ float Ms[64][64];

    const int tid = threadIdx.x;
    const float* Mg = g_m + ((size_t)(b * 16 + h)) * 4096;

    #pragma unroll
    for (int rep = 0; rep < 4; ++rep) {
        const int idx = tid + rep * 256;
        const int r = idx >> 4, c = (idx & 15) * 4;
        float4 v = *(const float4*)&Mg[r * 64 + c];
        Ms[r][c + 0] = v.x * scale;
        Ms[r][c + 1] = v.y * scale;
        Ms[r][c + 2] = v.z * scale;
        Ms[r][c + 3] = v.w * scale;
    }
    #pragma unroll
    for (int rep = 0; rep < 8; ++rep) {
        const int idx = tid + rep * 256;
        const int i = idx >> 4, kk0 = (idx & 15) * 4;
        float4 w = *(const float4*)&qw[(size_t)(it * 128 + i) * HIDDEN + h * 64 + kk0];
        Wt[kk0 + 0][i] = w.x;
        Wt[kk0 + 1][i] = w.y;
        Wt[kk0 + 2][i] = w.z;
        Wt[kk0 + 3][i] = w.w;
    }
    __syncthreads();

    const int i0 = (tid >> 4) * 8;
    const int d0 = (tid & 15) * 4;
    float acc[8][4] = {};
    #pragma unroll 8
    for (int kk = 0; kk < 64; ++kk) {
        float4 a0 = *(const float4*)&Wt[kk][i0];
        float4 a1 = *(const float4*)&Wt[kk][i0 + 4];
        float4 b4 = *(const float4*)&Ms[kk][d0];
        float a[8] = {a0.x, a0.y, a0.z, a0.w, a1.x, a1.y, a1.z, a1.w};
        float bb[4] = {b4.x, b4.y, b4.z, b4.w};
        #pragma unroll
        for (int i = 0; i < 8; ++i)
            #pragma unroll
            for (int j = 0; j < 4; ++j) acc[i][j] += a[i] * bb[j];
    }

    __half* W2h = g_w2h + (size_t)b * HIDDEN * HIDDEN;
    __half* W2l = g_w2l + (size_t)b * HIDDEN * HIDDEN;
    #pragma unroll
    for (int j = 0; j < 4; ++j) {
        union U8 { __half v[8]; uint4 u; } uh, ul;
        #pragma unroll
        for (int i = 0; i < 8; ++i) {
            HF2 s = hsplit(acc[i][j]);
            uh.v[i] = s.h;
            ul.v[i] = s.l;
        }
        const size_t o = (size_t)(h * 64 + d0 + j) * HIDDEN + it * 128 + i0;
        *(uint4*)&W2h[o] = uh.u;
        *(uint4*)&W2l[o] = ul.u;
    }
}

__global__ __launch_bounds__(256) void fold_b_kernel(const float* __restrict__ qb)
{
    const int idx = blockIdx.x * 256 + threadIdx.x;
    const int b = idx >> 10;
    const int hd = idx & 1023;
    const int h = hd >> 6, d = hd & 63;
    const float* M = g_m + ((size_t)(b * 16 + h)) * 4096;
    float s = 0.0f;
    #pragma unroll
    for (int k = 0; k < 64; ++k) s += qb[h * 64 + k] * M[k * 64 + d];
    g_b2[idx] = s * 0.125f;
}

// ---------------------------------------------------------------------------
extern "C" void kernel_launch(void* const* d_in, const int* in_sizes, int n_in,
                              void* d_out, int out_size)
{
    const float* query = (const float*)d_in[0];
    const float* key   = (const float*)d_in[1];
    const float* value = (const float*)d_in[2];
    const float* q_w   = (const float*)d_in[3];
    const float* q_b   = (const float*)d_in[4];
    const float* k_w   = (const float*)d_in[5];
    const float* k_b   = (const float*)d_in[6];
    const float* v_w   = (const float*)d_in[7];
    const float* v_b   = (const float*)d_in[8];
    float* out = (float*)d_out;

    // 1) f16 hi/lo conversions
    convert_x<<<dim3(4096, 1, 3), 256>>>(query, key, value);
    transpose_w<<<dim3(32, 32, 2), dim3(32, 8)>>>(k_w, v_w);

    // 2) K and V projections (HMMA) -> fp32 g_k, g_v
    gemm3<<<dim3(8, 64, 2), 256>>>(k_b, v_b, out, 0);

    // 3) M = K^T V per (b,h)
    m_partial_kernel<<<dim3(NSLICE, 64), 256>>>();
    m_reduce_kernel<<<(64 * 4096) / 256, 256>>>();

    // 4) fold M into Q projection (emit W2^T f16 hi/lo + fp32 b2)
    fold_w_kernel<<<dim3(8, HEADS, BATCH), 256>>>(q_w);
    fold_b_kernel<<<16, 256>>>(q_b);

    // 5) out = query @ W2_b + b2 (HMMA, per-batch B)
    gemm3<<<dim3(8, 64, 1), 256>>>(k_b, v_b, out, 1);
}

// round 9
// speedup vs baseline: 5.6056x; 1.3133x over previous
#include <cuda_runtime.h>
#include <cuda_fp16.h>
#include <cstdint>

#define HIDDEN 1024
#define HEADS 16
#define HEAD_DIM 64
#define BATCH 4
#define SEQ 2048
#define BSZ (BATCH * SEQ) /* 8192 */
#define NSLICE 8

// ---------------- scratch (__device__ globals: allocation-guard safe) ------
// NOTE: referenced from device code ONLY (host-side symbol = host shadow; GB300
// ATS silently reads host BSS zeros — the R5-R7 bug).
__device__ __align__(16) __half g_qh[(size_t)BSZ * HIDDEN], g_ql[(size_t)BSZ * HIDDEN];
__device__ __align__(16) __half g_kxh[(size_t)BSZ * HIDDEN], g_kxl[(size_t)BSZ * HIDDEN];
__device__ __align__(16) __half g_vxh[(size_t)BSZ * HIDDEN], g_vxl[(size_t)BSZ * HIDDEN];
__device__ __align__(16) __half g_wkh[(size_t)HIDDEN * HIDDEN], g_wkl[(size_t)HIDDEN * HIDDEN];
__device__ __align__(16) __half g_wvh[(size_t)HIDDEN * HIDDEN], g_wvl[(size_t)HIDDEN * HIDDEN];
__device__ __align__(16) __half g_w2h[(size_t)BATCH * HIDDEN * HIDDEN];
__device__ __align__(16) __half g_w2l[(size_t)BATCH * HIDDEN * HIDDEN];
__device__ float g_k[(size_t)BSZ * HIDDEN];   // K projection (fp32)
__device__ float g_v[(size_t)BSZ * HIDDEN];   // V projection (fp32)
__device__ float g_mp[(size_t)NSLICE * 64 * 64 * 64];
__device__ float g_m[(size_t)64 * 64 * 64];
__device__ float g_b2[(size_t)BATCH * HIDDEN];

// ---------------- PTX helpers (compute_103 base-target safe) ---------------
__device__ __forceinline__ uint32_t smem_u32(const void* p) {
    uint32_t a;
    asm("{ .reg .u64 t; cvta.to.shared.u64 t, %1; cvt.u32.u64 %0, t; }" : "=r"(a) : "l"(p));
    return a;
}
#define LDSM_X4(r, addr) \
    asm volatile("ldmatrix.sync.aligned.m8n8.x4.shared.b16 {%0,%1,%2,%3}, [%4];" \
        : "=r"((r)[0]), "=r"((r)[1]), "=r"((r)[2]), "=r"((r)[3]) : "r"(addr))
#define MMA16816(d, a, b) \
    asm volatile("mma.sync.aligned.m16n8k16.row.col.f32.f16.f16.f32 " \
        "{%0,%1,%2,%3}, {%4,%5,%6,%7}, {%8,%9}, {%0,%1,%2,%3};" \
        : "+f"((d)[0]), "+f"((d)[1]), "+f"((d)[2]), "+f"((d)[3]) \
        : "r"((a)[0]), "r"((a)[1]), "r"((a)[2]), "r"((a)[3]), \
          "r"((b)[0]), "r"((b)[1]))

// f16 hi/lo split: x = h + l, combined ~22-bit mantissa
struct HF2 { __half h, l; };
__device__ __forceinline__ HF2 hsplit(float x) {
    HF2 r;
    r.h = __float2half_rn(x);
    r.l = __float2half_rn(x - __half2float(r.h));
    return r;
}

// ---------------------------------------------------------------------------
// convert_x: fp32 [8192x1024] -> f16 hi/lo. z: 0=query 1=key 2=value
// ---------------------------------------------------------------------------
__global__ __launch_bounds__(256) void convert_x(
    const float* __restrict__ q, const float* __restrict__ k, const float* __restrict__ v)
{
    const float* x; __half *oh, *ol;
    if (blockIdx.z == 0)      { x = q; oh = g_qh;  ol = g_ql;  }
    else if (blockIdx.z == 1) { x = k; oh = g_kxh; ol = g_kxl; }
    else                      { x = v; oh = g_vxh; ol = g_vxl; }

    const size_t i8 = ((size_t)blockIdx.x * 256 + threadIdx.x) * 8;
    float4 a = *(const float4*)&x[i8];
    float4 b = *(const float4*)&x[i8 + 4];
    float f[8] = {a.x, a.y, a.z, a.w, b.x, b.y, b.z, b.w};
    union U8 { __half v[8]; uint4 u; } uh, ul;
    #pragma unroll
    for (int i = 0; i < 8; ++i) { HF2 s = hsplit(f[i]); uh.v[i] = s.h; ul.v[i] = s.l; }
    *(uint4*)&oh[i8] = uh.u;
    *(uint4*)&ol[i8] = ul.u;
}

// ---------------------------------------------------------------------------
// transpose_w: W[k][n] fp32 -> Wt hi/lo [n][k] f16. z: 0=k_w 1=v_w
// ---------------------------------------------------------------------------
__global__ void transpose_w(const float* __restrict__ kw, const float* __restrict__ vw)
{
    const float* W; __half *oh, *ol;
    if (blockIdx.z == 0) { W = kw; oh = g_wkh; ol = g_wkl; }
    else                 { W = vw; oh = g_wvh; ol = g_wvl; }

    __shared__ float t[32][33];
    const int tx = threadIdx.x, ty = threadIdx.y;
    const int kt = blockIdx.x * 32, nt = blockIdx.y * 32;

    #pragma unroll
    for (int r = 0; r < 4; ++r)
        t[ty + r * 8][tx] = W[(size_t)(kt + ty + r * 8) * HIDDEN + nt + tx];
    __syncthreads();
    #pragma unroll
    for (int r = 0; r < 4; ++r) {
        HF2 s = hsplit(t[tx][ty + r * 8]);
        const size_t o = (size_t)(nt + ty + r * 8) * HIDDEN + kt + tx;
        oh[o] = s.h;
        ol[o] = s.l;
    }
}

// ---------------------------------------------------------------------------
// HMMA GEMM (m16n8k16 f16, fp32 acc, 3-term hi/lo split):
//   C[m][n] = sum_k A[m][k]*B[n][k] + bias[n]
// mode 0: blockIdx.z 0 -> K proj, 1 -> V proj ; mode 1: out GEMM (per-batch B)
// CTA 128x128, 8 warps (2x4), warp tile 64x32, BK=16, reg double buffer.
// Fragments via ldmatrix.x4 (12 ops/warp/chunk vs 40 scalar LDS).
// 48B row stride -> 8-row ldmatrix groups hit distinct banks.
// ---------------------------------------------------------------------------
#define BK 16
#define RSTR 48                  /* bytes per smem row: 16 f16 + 8 pad */
#define MTILE (128 * RSTR)       /* 6144 B per matrix tile */
#define STAGEB (4 * MTILE)       /* 24576 B: Ah, Al, Bh, Bl */
#define NCH (HIDDEN / BK)        /* 64 chunks */

__global__ __launch_bounds__(256) void gemm3(
    const float* __restrict__ kb, const float* __restrict__ vb,
    float* __restrict__ out, int mode)
{
    __shared__ __align__(16) char sm[2 * STAGEB];   // 49152 B static
    const uint32_t sb = smem_u32(sm);

    const int tid = threadIdx.x;
    const int lane = tid & 31;
    const int g = lane >> 2;         // 0..7
    const int t = lane & 3;          // 0..3
    const int wid = tid >> 5;
    const int warp_m = wid >> 2;     // 0..1
    const int warp_n = wid & 3;      // 0..3
    const int m0 = blockIdx.y * 128;
    const int n0 = blockIdx.x * 128;

    const __half *Ah, *Al, *Bh, *Bl; const float* bias; float* C;
    if (mode == 0) {
        if (blockIdx.z == 0) {
            Ah = g_kxh; Al = g_kxl; Bh = g_wkh; Bl = g_wkl; bias = kb; C = g_k;
        } else {
            Ah = g_vxh; Al = g_vxl; Bh = g_wvh; Bl = g_wvl; bias = vb; C = g_v;
        }
    } else {
        const int bb = m0 >> 11;     // 2048 rows per batch
        Ah = g_qh; Al = g_ql;
        Bh = g_w2h + (size_t)bb * HIDDEN * HIDDEN;
        Bl = g_w2l + (size_t)bb * HIDDEN * HIDDEN;
        bias = g_b2 + (size_t)bb * HIDDEN;
        C = out;
    }

    // Per-thread load slots: idx = tid + it*256 in 0..1023
    const int slot_r = (tid & 255) >> 1;   // row 0..127
    const int slot_s = tid & 1;            // 16B segment

    auto gload = [&](int chunk, uint4* rg) {
        const int k0 = chunk * BK;
        #pragma unroll
        for (int it = 0; it < 4; ++it) {
            const int mat = (tid + it * 256) >> 8;
            const __half* src;
            if (mat == 0)      src = Ah + (size_t)(m0 + slot_r) * HIDDEN;
            else if (mat == 1) src = Al + (size_t)(m0 + slot_r) * HIDDEN;
            else if (mat == 2) src = Bh + (size_t)(n0 + slot_r) * HIDDEN;
            else               src = Bl + (size_t)(n0 + slot_r) * HIDDEN;
            rg[it] = *(const uint4*)(src + k0 + slot_s * 8);
        }
    };
    auto sstore = [&](int stage, const uint4* rg) {
        #pragma unroll
        for (int it = 0; it < 4; ++it) {
            const int mat = (tid + it * 256) >> 8;
            *(uint4*)(sm + stage * STAGEB + mat * MTILE + slot_r * RSTR + slot_s * 16)
                = rg[it];
        }
    };

    float acc[4][4][4];
    #pragma unroll
    for (int i = 0; i < 4; ++i)
        #pragma unroll
        for (int j = 0; j < 4; ++j)
            #pragma unroll
            for (int e = 0; e < 4; ++e) acc[i][j][e] = 0.0f;

    {
        uint4 rg[4];
        gload(0, rg);
        sstore(0, rg);
    }
    __syncthreads();

    // ldmatrix lane address components
    // A (16x16 tile): lanes 0-7 rows 0-7 k0-7; 8-15 rows 8-15 k0-7;
    //                 16-23 rows 0-7 k8-15; 24-31 rows 8-15 k8-15
    const int a_lrow = lane & 15;          // row within 16-row tile
    const int a_lcol = (lane >> 4) * 16;   // byte offset (k half)
    // B (two 8-row n-tiles x k16): lanes 0-7 n0-7 k0-7; 8-15 n0-7 k8-15;
    //                              16-23 n8-15 k0-7; 24-31 n8-15 k8-15
    const int b_lrow = (lane & 7) + ((lane >> 4) << 3);
    const int b_lcol = ((lane >> 3) & 1) * 16;

    for (int c = 0; c < NCH; ++c) {
        uint4 rn[4];
        if (c + 1 < NCH) gload(c + 1, rn);   // LDG in flight over compute

        const uint32_t stg = sb + (c & 1) * STAGEB;

        uint32_t ah[4][4], al[4][4], bh[4][2], bl[4][2];
        #pragma unroll
        for (int i = 0; i < 4; ++i) {
            const uint32_t ra = stg + (warp_m * 64 + i * 16 + a_lrow) * RSTR + a_lcol;
            LDSM_X4(ah[i], ra);
            LDSM_X4(al[i], ra + MTILE);
        }
        #pragma unroll
        for (int j2 = 0; j2 < 2; ++j2) {
            uint32_t t4[4];
            const uint32_t rb = stg + 2 * MTILE +
                (warp_n * 32 + j2 * 16 + b_lrow) * RSTR + b_lcol;
            LDSM_X4(t4, rb);
            bh[2 * j2][0] = t4[0]; bh[2 * j2][1] = t4[1];
            bh[2 * j2 + 1][0] = t4[2]; bh[2 * j2 + 1][1] = t4[3];
            LDSM_X4(t4, rb + MTILE);
            bl[2 * j2][0] = t4[0]; bl[2 * j2][1] = t4[1];
            bl[2 * j2 + 1][0] = t4[2]; bl[2 * j2 + 1][1] = t4[3];
        }
        #pragma unroll
        for (int i = 0; i < 4; ++i)
            #pragma unroll
            for (int j = 0; j < 4; ++j) {
                MMA16816(acc[i][j], ah[i], bh[j]);
                MMA16816(acc[i][j], ah[i], bl[j]);
                MMA16816(acc[i][j], al[i], bh[j]);
            }

        if (c + 1 < NCH) sstore((c + 1) & 1, rn);  // idle stage
        __syncthreads();
    }

    // -------- epilogue: bias + fp32 stores --------
    #pragma unroll
    for (int j = 0; j < 4; ++j) {
        const int col = n0 + warp_n * 32 + j * 8 + t * 2;
        const float2 bv = *(const float2*)&bias[col];
        #pragma unroll
        for (int i = 0; i < 4; ++i) {
            const int row = m0 + warp_m * 64 + i * 16 + g;
            float2 v0 = make_float2(acc[i][j][0] + bv.x, acc[i][j][1] + bv.y);
            float2 v1 = make_float2(acc[i][j][2] + bv.x, acc[i][j][3] + bv.y);
            *(float2*)&C[(size_t)row * HIDDEN + col] = v0;
            *(float2*)&C[(size_t)(row + 8) * HIDDEN + col] = v1;
        }
    }
}

// ---------------------------------------------------------------------------
// m_partial: P[s][bh] = sum_{rows in slice} K[r,k]*V[r,d]; 32-row stages
// ---------------------------------------------------------------------------
__global__ __launch_bounds__(256) void m_partial_kernel()
{
    const int s = blockIdx.x, bh = blockIdx.y;
    const int b = bh >> 4, h = bh & 15;
    const size_t off = (size_t)b * SEQ * HIDDEN + (size_t)h * HEAD_DIM;
    const float* Kg = g_k + off;
    const float* Vg = g_v + off;

    __shared__ float Ks[32][64], Vs[32][64];
    const int tid = threadIdx.x;
    const int k0 = (tid >> 4) * 4, d0 = (tid & 15) * 4;
    const int lr = tid >> 3;            // load row 0..31
    const int ld = (tid & 7) * 8;       // 8 floats per thread

    float acc[4][4] = {};
    const int rbeg = s * (SEQ / NSLICE);
    for (int r0 = rbeg; r0 < rbeg + SEQ / NSLICE; r0 += 32) {
        __syncthreads();
        const float* kp = &Kg[(size_t)(r0 + lr) * HIDDEN + ld];
        const float* vp = &Vg[(size_t)(r0 + lr) * HIDDEN + ld];
        *(float4*)&Ks[lr][ld]     = *(const float4*)kp;
        *(float4*)&Ks[lr][ld + 4] = *(const float4*)(kp + 4);
        *(float4*)&Vs[lr][ld]     = *(const float4*)vp;
        *(float4*)&Vs[lr][ld + 4] = *(const float4*)(vp + 4);
        __syncthreads();
        #pragma unroll 8
        for (int rr = 0; rr < 32; ++rr) {
            float4 a4 = *(const float4*)&Ks[rr][k0];
            float4 b4 = *(const float4*)&Vs[rr][d0];
            float a[4] = {a4.x, a4.y, a4.z, a4.w};
            float bb[4] = {b4.x, b4.y, b4.z, b4.w};
            #pragma unroll
            for (int i = 0; i < 4; ++i)
                #pragma unroll
                for (int j = 0; j < 4; ++j) acc[i][j] += a[i] * bb[j];
        }
    }
    float* P = g_mp + ((size_t)s * 64 + bh) * 4096;
    #pragma unroll
    for (int i = 0; i < 4; ++i)
        *(float4*)&P[(k0 + i) * 64 + d0] =
            make_float4(acc[i][0], acc[i][1], acc[i][2], acc[i][3]);
}

__global__ __launch_bounds__(256) void m_reduce_kernel()
{
    const int idx = blockIdx.x * 256 + threadIdx.x;
    float s = 0.0f;
    #pragma unroll
    for (int i = 0; i < NSLICE; ++i) s += g_mp[(size_t)i * 64 * 4096 + idx];
    g_m[idx] = s;
}

// ---------------------------------------------------------------------------
// fold_w: W2t[b][n][k] (f16 hi/lo) = (scale * Wq * blockdiag(M))^T
// ---------------------------------------------------------------------------
__global__ __launch_bounds__(256) void fold_w_kernel(const float* __restrict__ qw)
{
    const int it = blockIdx.x, h = blockIdx.y, b = blockIdx.z;
    const float scale = 0.125f;

    __shared__ float Wt[64][128];
    __shared__ float Ms[64][64];

    const int tid = threadIdx.x;
    const float* Mg = g_m + ((size_t)(b * 16 + h)) * 4096;

    #pragma unroll
    for (int rep = 0; rep < 4; ++rep) {
        const int idx = tid + rep * 256;
        const int r = idx >> 4, c = (idx & 15) * 4;
        float4 v = *(const float4*)&Mg[r * 64 + c];
        Ms[r][c + 0] = v.x * scale;
        Ms[r][c + 1] = v.y * scale;
        Ms[r][c + 2] = v.z * scale;
        Ms[r][c + 3] = v.w * scale;
    }
    #pragma unroll
    for (int rep = 0; rep < 8; ++rep) {
        const int idx = tid + rep * 256;
        const int i = idx >> 4, kk0 = (idx & 15) * 4;
        float4 w = *(const float4*)&qw[(size_t)(it * 128 + i) * HIDDEN + h * 64 + kk0];
        Wt[kk0 + 0][i] = w.x;
        Wt[kk0 + 1][i] = w.y;
        Wt[kk0 + 2][i] = w.z;
        Wt[kk0 + 3][i] = w.w;
    }
    __syncthreads();

    const int i0 = (tid >> 4) * 8;
    const int d0 = (tid & 15) * 4;
    float acc[8][4] = {};
    #pragma unroll 8
    for (int kk = 0; kk < 64; ++kk) {
        float4 a0 = *(const float4*)&Wt[kk][i0];
        float4 a1 = *(const float4*)&Wt[kk][i0 + 4];
        float4 b4 = *(const float4*)&Ms[kk][d0];
        float a[8] = {a0.x, a0.y, a0.z, a0.w, a1.x, a1.y, a1.z, a1.w};
        float bb[4] = {b4.x, b4.y, b4.z, b4.w};
        #pragma unroll
        for (int i = 0; i < 8; ++i)
            #pragma unroll
            for (int j = 0; j < 4; ++j) acc[i][j] += a[i] * bb[j];
    }

    __half* W2h = g_w2h + (size_t)b * HIDDEN * HIDDEN;
    __half* W2l = g_w2l + (size_t)b * HIDDEN * HIDDEN;
    #pragma unroll
    for (int j = 0; j < 4; ++j) {
        union U8 { __half v[8]; uint4 u; } uh, ul;
        #pragma unroll
        for (int i = 0; i < 8; ++i) {
            HF2 s = hsplit(acc[i][j]);
            uh.v[i] = s.h;
            ul.v[i] = s.l;
        }
        const size_t o = (size_t)(h * 64 + d0 + j) * HIDDEN + it * 128 + i0;
        *(uint4*)&W2h[o] = uh.u;
        *(uint4*)&W2l[o] = ul.u;
    }
}

__global__ __launch_bounds__(256) void fold_b_kernel(const float* __restrict__ qb)
{
    const int idx = blockIdx.x * 256 + threadIdx.x;
    const int b = idx >> 10;
    const int hd = idx & 1023;
    const int h = hd >> 6, d = hd & 63;
    const float* M = g_m + ((size_t)(b * 16 + h)) * 4096;
    float s = 0.0f;
    #pragma unroll
    for (int k = 0; k < 64; ++k) s += qb[h * 64 + k] * M[k * 64 + d];
    g_b2[idx] = s * 0.125f;
}

// ---------------------------------------------------------------------------
extern "C" void kernel_launch(void* const* d_in, const int* in_sizes, int n_in,
                              void* d_out, int out_size)
{
    const float* query = (const float*)d_in[0];
    const float* key   = (const float*)d_in[1];
    const float* value = (const float*)d_in[2];
    const float* q_w   = (const float*)d_in[3];
    const float* q_b   = (const float*)d_in[4];
    const float* k_w   = (const float*)d_in[5];
    const float* k_b   = (const float*)d_in[6];
    const float* v_w   = (const float*)d_in[7];
    const float* v_b   = (const float*)d_in[8];
    float* out = (float*)d_out;

    // 1) f16 hi/lo conversions
    convert_x<<<dim3(4096, 1, 3), 256>>>(query, key, value);
    transpose_w<<<dim3(32, 32, 2), dim3(32, 8)>>>(k_w, v_w);

    // 2) K and V projections (HMMA) -> fp32 g_k, g_v
    gemm3<<<dim3(8, 64, 2), 256>>>(k_b, v_b, out, 0);

    // 3) M = K^T V per (b,h)
    m_partial_kernel<<<dim3(NSLICE, 64), 256>>>();
    m_reduce_kernel<<<(64 * 4096) / 256, 256>>>();

    // 4) fold M into Q projection (emit W2^T f16 hi/lo + fp32 b2)
    fold_w_kernel<<<dim3(8, HEADS, BATCH), 256>>>(q_w);
    fold_b_kernel<<<16, 256>>>(q_b);

    // 5) out = query @ W2_b + b2 (HMMA, per-batch B)
    gemm3<<<dim3(8, 64, 1), 256>>>(k_b, v_b, out, 1);
}

// round 10
// speedup vs baseline: 5.6284x; 1.0041x over previous
#include <cuda_runtime.h>
#include <cuda_fp16.h>
#include <cstdint>

#define HIDDEN 1024
#define HEADS 16
#define HEAD_DIM 64
#define BATCH 4
#define SEQ 2048
#define BSZ (BATCH * SEQ) /* 8192 */
#define NSLICE 8

// ---------------- scratch (__device__ globals: allocation-guard safe) ------
// NOTE: referenced from device code ONLY (host-side symbol = host shadow; GB300
// ATS silently reads host BSS zeros — the R5-R7 bug).
__device__ __align__(16) __half g_qh[(size_t)BSZ * HIDDEN], g_ql[(size_t)BSZ * HIDDEN];
__device__ __align__(16) __half g_kxh[(size_t)BSZ * HIDDEN], g_kxl[(size_t)BSZ * HIDDEN];
__device__ __align__(16) __half g_vxh[(size_t)BSZ * HIDDEN], g_vxl[(size_t)BSZ * HIDDEN];
__device__ __align__(16) __half g_wkh[(size_t)HIDDEN * HIDDEN], g_wkl[(size_t)HIDDEN * HIDDEN];
__device__ __align__(16) __half g_wvh[(size_t)HIDDEN * HIDDEN], g_wvl[(size_t)HIDDEN * HIDDEN];
__device__ __align__(16) __half g_w2h[(size_t)BATCH * HIDDEN * HIDDEN];
__device__ __align__(16) __half g_w2l[(size_t)BATCH * HIDDEN * HIDDEN];
__device__ float g_k[(size_t)BSZ * HIDDEN];   // K projection (fp32)
__device__ float g_v[(size_t)BSZ * HIDDEN];   // V projection (fp32)
__device__ float g_mp[(size_t)NSLICE * 64 * 64 * 64];
__device__ float g_m[(size_t)64 * 64 * 64];
__device__ float g_b2[(size_t)BATCH * HIDDEN];

// ---------------- PTX helpers (compute_103 base-target safe) ---------------
__device__ __forceinline__ uint32_t smem_u32(const void* p) {
    uint32_t a;
    asm("{ .reg .u64 t; cvta.to.shared.u64 t, %1; cvt.u32.u64 %0, t; }" : "=r"(a) : "l"(p));
    return a;
}
__device__ __forceinline__ uint64_t gaddr(const void* p) {
    uint64_t a;
    asm("cvta.to.global.u64 %0, %1;" : "=l"(a) : "l"(p));
    return a;
}
#define CPA16(sa, ga) \
    asm volatile("cp.async.cg.shared.global [%0], [%1], 16;" :: "r"(sa), "l"(ga) : "memory")
#define CP_COMMIT() asm volatile("cp.async.commit_group;" ::: "memory")
#define CP_WAIT1()  asm volatile("cp.async.wait_group 1;" ::: "memory")
#define LDSM_X4(r, addr) \
    asm volatile("ldmatrix.sync.aligned.m8n8.x4.shared.b16 {%0,%1,%2,%3}, [%4];" \
        : "=r"((r)[0]), "=r"((r)[1]), "=r"((r)[2]), "=r"((r)[3]) : "r"(addr))
#define MMA16816(d, a, b) \
    asm volatile("mma.sync.aligned.m16n8k16.row.col.f32.f16.f16.f32 " \
        "{%0,%1,%2,%3}, {%4,%5,%6,%7}, {%8,%9}, {%0,%1,%2,%3};" \
        : "+f"((d)[0]), "+f"((d)[1]), "+f"((d)[2]), "+f"((d)[3]) \
        : "r"((a)[0]), "r"((a)[1]), "r"((a)[2]), "r"((a)[3]), \
          "r"((b)[0]), "r"((b)[1]))

// f16 hi/lo split: x = h + l, combined ~22-bit mantissa
struct HF2 { __half h, l; };
__device__ __forceinline__ HF2 hsplit(float x) {
    HF2 r;
    r.h = __float2half_rn(x);
    r.l = __float2half_rn(x - __half2float(r.h));
    return r;
}

// ---------------------------------------------------------------------------
// convert_x: fp32 [8192x1024] -> f16 hi/lo. z: 0=query 1=key 2=value
// ---------------------------------------------------------------------------
__global__ __launch_bounds__(256) void convert_x(
    const float* __restrict__ q, const float* __restrict__ k, const float* __restrict__ v)
{
    const float* x; __half *oh, *ol;
    if (blockIdx.z == 0)      { x = q; oh = g_qh;  ol = g_ql;  }
    else if (blockIdx.z == 1) { x = k; oh = g_kxh; ol = g_kxl; }
    else                      { x = v; oh = g_vxh; ol = g_vxl; }

    const size_t i8 = ((size_t)blockIdx.x * 256 + threadIdx.x) * 8;
    float4 a = *(const float4*)&x[i8];
    float4 b = *(const float4*)&x[i8 + 4];
    float f[8] = {a.x, a.y, a.z, a.w, b.x, b.y, b.z, b.w};
    union U8 { __half v[8]; uint4 u; } uh, ul;
    #pragma unroll
    for (int i = 0; i < 8; ++i) { HF2 s = hsplit(f[i]); uh.v[i] = s.h; ul.v[i] = s.l; }
    *(uint4*)&oh[i8] = uh.u;
    *(uint4*)&ol[i8] = ul.u;
}

// ---------------------------------------------------------------------------
// transpose_w: W[k][n] fp32 -> Wt hi/lo [n][k] f16. z: 0=k_w 1=v_w
// ---------------------------------------------------------------------------
__global__ void transpose_w(const float* __restrict__ kw, const float* __restrict__ vw)
{
    const float* W; __half *oh, *ol;
    if (blockIdx.z == 0) { W = kw; oh = g_wkh; ol = g_wkl; }
    else                 { W = vw; oh = g_wvh; ol = g_wvl; }

    __shared__ float t[32][33];
    const int tx = threadIdx.x, ty = threadIdx.y;
    const int kt = blockIdx.x * 32, nt = blockIdx.y * 32;

    #pragma unroll
    for (int r = 0; r < 4; ++r)
        t[ty + r * 8][tx] = W[(size_t)(kt + ty + r * 8) * HIDDEN + nt + tx];
    __syncthreads();
    #pragma unroll
    for (int r = 0; r < 4; ++r) {
        HF2 s = hsplit(t[tx][ty + r * 8]);
        const size_t o = (size_t)(nt + ty + r * 8) * HIDDEN + kt + tx;
        oh[o] = s.h;
        ol[o] = s.l;
    }
}

// ---------------------------------------------------------------------------
// HMMA GEMM (m16n8k16 f16, fp32 acc, 3-term hi/lo split):
//   C[m][n] = sum_k A[m][k]*B[n][k] + bias[n]
// mode 0: blockIdx.z 0 -> K proj, 1 -> V proj ; mode 1: out GEMM (per-batch B)
// CTA 128x128, 8 warps (2x4), warp tile 64x32, BK=16.
// cp.async 3-stage pipeline (72KB dynamic smem), one __syncthreads per chunk,
// __launch_bounds__(256,2) for 2 CTAs/SM. ldmatrix fragments; 48B row stride.
// ---------------------------------------------------------------------------
#define BK 16
#define RSTR 48                  /* bytes per smem row: 16 f16 + 8 pad */
#define MTILE (128 * RSTR)       /* 6144 B per matrix tile */
#define STAGEB (4 * MTILE)       /* 24576 B: Ah, Al, Bh, Bl */
#define NSTAGE 3
#define GSMEM (NSTAGE * STAGEB)  /* 73728 B dynamic */
#define NCH (HIDDEN / BK)        /* 64 chunks */

__global__ __launch_bounds__(256, 2) void gemm3(
    const float* __restrict__ kb, const float* __restrict__ vb,
    float* __restrict__ out, int mode)
{
    extern __shared__ __align__(16) char sm[];
    const uint32_t sb = smem_u32(sm);

    const int tid = threadIdx.x;
    const int lane = tid & 31;
    const int g = lane >> 2;         // 0..7
    const int t = lane & 3;          // 0..3
    const int wid = tid >> 5;
    const int warp_m = wid >> 2;     // 0..1
    const int warp_n = wid & 3;      // 0..3
    const int m0 = blockIdx.y * 128;
    const int n0 = blockIdx.x * 128;

    const __half *Ah, *Al, *Bh, *Bl; const float* bias; float* C;
    if (mode == 0) {
        if (blockIdx.z == 0) {
            Ah = g_kxh; Al = g_kxl; Bh = g_wkh; Bl = g_wkl; bias = kb; C = g_k;
        } else {
            Ah = g_vxh; Al = g_vxl; Bh = g_wvh; Bl = g_wvl; bias = vb; C = g_v;
        }
    } else {
        const int bb = m0 >> 11;     // 2048 rows per batch
        Ah = g_qh; Al = g_ql;
        Bh = g_w2h + (size_t)bb * HIDDEN * HIDDEN;
        Bl = g_w2l + (size_t)bb * HIDDEN * HIDDEN;
        bias = g_b2 + (size_t)bb * HIDDEN;
        C = out;
    }

    // Per-thread load slot: each thread copies one 16B segment (row slot_r,
    // segment slot_s) from EACH of the 4 matrices.
    const int slot_r = tid >> 1;     // 0..127
    const int slot_s = tid & 1;      // 16B segment

    // Global base addresses (cvta once)
    uint64_t gsrc[4];
    gsrc[0] = gaddr(Ah + (size_t)(m0 + slot_r) * HIDDEN + slot_s * 8);
    gsrc[1] = gaddr(Al + (size_t)(m0 + slot_r) * HIDDEN + slot_s * 8);
    gsrc[2] = gaddr(Bh + (size_t)(n0 + slot_r) * HIDDEN + slot_s * 8);
    gsrc[3] = gaddr(Bl + (size_t)(n0 + slot_r) * HIDDEN + slot_s * 8);
    const uint32_t sdst0 = sb + slot_r * RSTR + slot_s * 16;

    auto issue = [&](int chunk, int stage) {
        const uint64_t goff = (uint64_t)chunk * BK * 2;  // bytes
        const uint32_t s0 = sdst0 + stage * STAGEB;
        #pragma unroll
        for (int mat = 0; mat < 4; ++mat)
            CPA16(s0 + mat * MTILE, gsrc[mat] + goff);
    };

    float acc[4][4][4];
    #pragma unroll
    for (int i = 0; i < 4; ++i)
        #pragma unroll
        for (int j = 0; j < 4; ++j)
            #pragma unroll
            for (int e = 0; e < 4; ++e) acc[i][j][e] = 0.0f;

    issue(0, 0); CP_COMMIT();
    issue(1, 1); CP_COMMIT();

    // ldmatrix lane address components
    const int a_lrow = lane & 15;          // row within 16-row tile
    const int a_lcol = (lane >> 4) * 16;   // k-half byte offset
    const int b_lrow = (lane & 7) + ((lane >> 4) << 3);
    const int b_lcol = ((lane >> 3) & 1) * 16;

    int stage = 0;
    for (int c = 0; c < NCH; ++c) {
        CP_WAIT1();            // group for chunk c complete (≤1 newer pending)
        __syncthreads();       // all warps see chunk c; prev compute done

        if (c + 2 < NCH) issue(c + 2, (c + 2) % NSTAGE);
        CP_COMMIT();           // empty group when none issued keeps ladder uniform

        const uint32_t stg = sb + stage * STAGEB;
        stage = (stage + 1 == NSTAGE) ? 0 : stage + 1;

        // B fragments resident (16 regs)
        uint32_t bh[4][2], bl[4][2];
        #pragma unroll
        for (int j2 = 0; j2 < 2; ++j2) {
            uint32_t t4[4];
            const uint32_t rb = stg + 2 * MTILE +
                (warp_n * 32 + j2 * 16 + b_lrow) * RSTR + b_lcol;
            LDSM_X4(t4, rb);
            bh[2 * j2][0] = t4[0]; bh[2 * j2][1] = t4[1];
            bh[2 * j2 + 1][0] = t4[2]; bh[2 * j2 + 1][1] = t4[3];
            LDSM_X4(t4, rb + MTILE);
            bl[2 * j2][0] = t4[0]; bl[2 * j2][1] = t4[1];
            bl[2 * j2 + 1][0] = t4[2]; bl[2 * j2 + 1][1] = t4[3];
        }
        // A fragments per i-tile (8 regs live)
        #pragma unroll
        for (int i = 0; i < 4; ++i) {
            uint32_t ah[4], al[4];
            const uint32_t ra = stg + (warp_m * 64 + i * 16 + a_lrow) * RSTR + a_lcol;
            LDSM_X4(ah, ra);
            LDSM_X4(al, ra + MTILE);
            #pragma unroll
            for (int j = 0; j < 4; ++j) {
                MMA16816(acc[i][j], ah, bh[j]);
                MMA16816(acc[i][j], ah, bl[j]);
                MMA16816(acc[i][j], al, bh[j]);
            }
        }
    }

    // -------- epilogue: bias + fp32 stores --------
    #pragma unroll
    for (int j = 0; j < 4; ++j) {
        const int col = n0 + warp_n * 32 + j * 8 + t * 2;
        const float2 bv = *(const float2*)&bias[col];
        #pragma unroll
        for (int i = 0; i < 4; ++i) {
            const int row = m0 + warp_m * 64 + i * 16 + g;
            float2 v0 = make_float2(acc[i][j][0] + bv.x, acc[i][j][1] + bv.y);
            float2 v1 = make_float2(acc[i][j][2] + bv.x, acc[i][j][3] + bv.y);
            *(float2*)&C[(size_t)row * HIDDEN + col] = v0;
            *(float2*)&C[(size_t)(row + 8) * HIDDEN + col] = v1;
        }
    }
}

// ---------------------------------------------------------------------------
// m_partial: P[s][bh] = sum_{rows in slice} K[r,k]*V[r,d]; 32-row stages
// ---------------------------------------------------------------------------
__global__ __launch_bounds__(256) void m_partial_kernel()
{
    const int s = blockIdx.x, bh = blockIdx.y;
    const int b = bh >> 4, h = bh & 15;
    const size_t off = (size_t)b * SEQ * HIDDEN + (size_t)h * HEAD_DIM;
    const float* Kg = g_k + off;
    const float* Vg = g_v + off;

    __shared__ float Ks[32][64], Vs[32][64];
    const int tid = threadIdx.x;
    const int k0 = (tid >> 4) * 4, d0 = (tid & 15) * 4;
    const int lr = tid >> 3;            // load row 0..31
    const int ld = (tid & 7) * 8;       // 8 floats per thread

    float acc[4][4] = {};
    const int rbeg = s * (SEQ / NSLICE);
    for (int r0 = rbeg; r0 < rbeg + SEQ / NSLICE; r0 += 32) {
        __syncthreads();
        const float* kp = &Kg[(size_t)(r0 + lr) * HIDDEN + ld];
        const float* vp = &Vg[(size_t)(r0 + lr) * HIDDEN + ld];
        *(float4*)&Ks[lr][ld]     = *(const float4*)kp;
        *(float4*)&Ks[lr][ld + 4] = *(const float4*)(kp + 4);
        *(float4*)&Vs[lr][ld]     = *(const float4*)vp;
        *(float4*)&Vs[lr][ld + 4] = *(const float4*)(vp + 4);
        __syncthreads();
        #pragma unroll 8
        for (int rr = 0; rr < 32; ++rr) {
            float4 a4 = *(const float4*)&Ks[rr][k0];
            float4 b4 = *(const float4*)&Vs[rr][d0];
            float a[4] = {a4.x, a4.y, a4.z, a4.w};
            float bb[4] = {b4.x, b4.y, b4.z, b4.w};
            #pragma unroll
            for (int i = 0; i < 4; ++i)
                #pragma unroll
                for (int j = 0; j < 4; ++j) acc[i][j] += a[i] * bb[j];
        }
    }
    float* P = g_mp + ((size_t)s * 64 + bh) * 4096;
    #pragma unroll
    for (int i = 0; i < 4; ++i)
        *(float4*)&P[(k0 + i) * 64 + d0] =
            make_float4(acc[i][0], acc[i][1], acc[i][2], acc[i][3]);
}

__global__ __launch_bounds__(256) void m_reduce_kernel()
{
    const int idx = blockIdx.x * 256 + threadIdx.x;
    float s = 0.0f;
    #pragma unroll
    for (int i = 0; i < NSLICE; ++i) s += g_mp[(size_t)i * 64 * 4096 + idx];
    g_m[idx] = s;
}

// ---------------------------------------------------------------------------
// fold_w: W2t[b][n][k] (f16 hi/lo) = (scale * Wq * blockdiag(M))^T
// ---------------------------------------------------------------------------
__global__ __launch_bounds__(256) void fold_w_kernel(const float* __restrict__ qw)
{
    const int it = blockIdx.x, h = blockIdx.y, b = blockIdx.z;
    const float scale = 0.125f;

    __shared__ float Wt[64][128];
    __shared__ float Ms[64][64];

    const int tid = threadIdx.x;
    const float* Mg = g_m + ((size_t)(b * 16 + h)) * 4096;

    #pragma unroll
    for (int rep = 0; rep < 4; ++rep) {
        const int idx = tid + rep * 256;
        const int r = idx >> 4, c = (idx & 15) * 4;
        float4 v = *(const float4*)&Mg[r * 64 + c];
        Ms[r][c + 0] = v.x * scale;
        Ms[r][c + 1] = v.y * scale;
        Ms[r][c + 2] = v.z * scale;
        Ms[r][c + 3] = v.w * scale;
    }
    #pragma unroll
    for (int rep = 0; rep < 8; ++rep) {
        const int idx = tid + rep * 256;
        const int i = idx >> 4, kk0 = (idx & 15) * 4;
        float4 w = *(const float4*)&qw[(size_t)(it * 128 + i) * HIDDEN + h * 64 + kk0];
        Wt[kk0 + 0][i] = w.x;
        Wt[kk0 + 1][i] = w.y;
        Wt[kk0 + 2][i] = w.z;
        Wt[kk0 + 3][i] = w.w;
    }
    __syncthreads();

    const int i0 = (tid >> 4) * 8;
    const int d0 = (tid & 15) * 4;
    float acc[8][4] = {};
    #pragma unroll 8
    for (int kk = 0; kk < 64; ++kk) {
        float4 a0 = *(const float4*)&Wt[kk][i0];
        float4 a1 = *(const float4*)&Wt[kk][i0 + 4];
        float4 b4 = *(const float4*)&Ms[kk][d0];
        float a[8] = {a0.x, a0.y, a0.z, a0.w, a1.x, a1.y, a1.z, a1.w};
        float bb[4] = {b4.x, b4.y, b4.z, b4.w};
        #pragma unroll
        for (int i = 0; i < 8; ++i)
            #pragma unroll
            for (int j = 0; j < 4; ++j) acc[i][j] += a[i] * bb[j];
    }

    __half* W2h = g_w2h + (size_t)b * HIDDEN * HIDDEN;
    __half* W2l = g_w2l + (size_t)b * HIDDEN * HIDDEN;
    #pragma unroll
    for (int j = 0; j < 4; ++j) {
        union U8 { __half v[8]; uint4 u; } uh, ul;
        #pragma unroll
        for (int i = 0; i < 8; ++i) {
            HF2 s = hsplit(acc[i][j]);
            uh.v[i] = s.h;
            ul.v[i] = s.l;
        }
        const size_t o = (size_t)(h * 64 + d0 + j) * HIDDEN + it * 128 + i0;
        *(uint4*)&W2h[o] = uh.u;
        *(uint4*)&W2l[o] = ul.u;
    }
}

__global__ __launch_bounds__(256) void fold_b_kernel(const float* __restrict__ qb)
{
    const int idx = blockIdx.x * 256 + threadIdx.x;
    const int b = idx >> 10;
    const int hd = idx & 1023;
    const int h = hd >> 6, d = hd & 63;
    const float* M = g_m + ((size_t)(b * 16 + h)) * 4096;
    float s = 0.0f;
    #pragma unroll
    for (int k = 0; k < 64; ++k) s += qb[h * 64 + k] * M[k * 64 + d];
    g_b2[idx] = s * 0.125f;
}

// ---------------------------------------------------------------------------
extern "C" void kernel_launch(void* const* d_in, const int* in_sizes, int n_in,
                              void* d_out, int out_size)
{
    const float* query = (const float*)d_in[0];
    const float* key   = (const float*)d_in[1];
    const float* value = (const float*)d_in[2];
    const float* q_w   = (const float*)d_in[3];
    const float* q_b   = (const float*)d_in[4];
    const float* k_w   = (const float*)d_in[5];
    const float* k_b   = (const float*)d_in[6];
    const float* v_w   = (const float*)d_in[7];
    const float* v_b   = (const float*)d_in[8];
    float* out = (float*)d_out;

    cudaFuncSetAttribute(gemm3, cudaFuncAttributeMaxDynamicSharedMemorySize, GSMEM);

    // 1) f16 hi/lo conversions
    convert_x<<<dim3(4096, 1, 3), 256>>>(query, key, value);
    transpose_w<<<dim3(32, 32, 2), dim3(32, 8)>>>(k_w, v_w);

    // 2) K and V projections (HMMA) -> fp32 g_k, g_v
    gemm3<<<dim3(8, 64, 2), 256, GSMEM>>>(k_b, v_b, out, 0);

    // 3) M = K^T V per (b,h)
    m_partial_kernel<<<dim3(NSLICE, 64), 256>>>();
    m_reduce_kernel<<<(64 * 4096) / 256, 256>>>();

    // 4) fold M into Q projection (emit W2^T f16 hi/lo + fp32 b2)
    fold_w_kernel<<<dim3(8, HEADS, BATCH), 256>>>(q_w);
    fold_b_kernel<<<16, 256>>>(q_b);

    // 5) out = query @ W2_b + b2 (HMMA, per-batch B)
    gemm3<<<dim3(8, 64, 1), 256, GSMEM>>>(k_b, v_b, out, 1);
}